// round 1
// baseline (speedup 1.0000x reference)
#include <cuda_runtime.h>

#define HEADS 4
#define DHEAD 32
#define HID 128
#define CIN 64
#define NPOS 4096
#define NSPLIT 8
#define CHUNK (NPOS / NSPLIT) /* 512 */
#define L2E 1.4426950408889634f

// ---- device scratch (allocation-free: static __device__ globals) ----
__device__ __align__(16) float g_qt[HEADS * NPOS * DHEAD];   // scaled Q, [h][n][d]
__device__ __align__(16) float g_kt[HEADS * NPOS * DHEAD];   // [h][n][d]
__device__ __align__(16) float g_vt[HEADS * NPOS * DHEAD];   // [h][n][d]
__device__ float g_pm[HEADS * NPOS * NSPLIT];
__device__ float g_pl[HEADS * NPOS * NSPLIT];
__device__ __align__(16) float g_pacc[HEADS * NPOS * NSPLIT * DHEAD];
__device__ __align__(16) float g_o[HID * NPOS];              // attention out, [c][n], c=h*32+d

// ============================================================
// Kernel 1: QKV = w_qkv @ x   (384x64 * 64x4096), write transposed tiles
// grid (32, 48), block 128. Each thread: 1 n, 8 consecutive o.
// ============================================================
__global__ void qkv_kernel(const float* __restrict__ x, const float* __restrict__ w)
{
    int n = blockIdx.x * 128 + threadIdx.x;
    int og = blockIdx.y * 8;

    __shared__ float ws[8 * 64];
    for (int idx = threadIdx.x; idx < 8 * 64; idx += 128)
        ws[idx] = w[og * 64 + idx];
    __syncthreads();

    float acc[8];
#pragma unroll
    for (int k = 0; k < 8; k++) acc[k] = 0.f;

#pragma unroll 4
    for (int c = 0; c < CIN; c++) {
        float xv = x[c * NPOS + n];
#pragma unroll
        for (int k = 0; k < 8; k++) acc[k] += ws[k * 64 + c] * xv;
    }

    int seg = og >> 7;          // 0=q 1=k 2=v
    int oo = og & 127;
    int h = oo >> 5, d0 = oo & 31;
    float scale = (seg == 0) ? 0.17677669529663687f : 1.f;  // 32^-0.5
    float* base = (seg == 0) ? g_qt : ((seg == 1) ? g_kt : g_vt);

    float4 a = make_float4(acc[0] * scale, acc[1] * scale, acc[2] * scale, acc[3] * scale);
    float4 b = make_float4(acc[4] * scale, acc[5] * scale, acc[6] * scale, acc[7] * scale);
    float* p = base + (size_t)(h * NPOS + n) * DHEAD + d0;
    *(float4*)p = a;
    *(float4*)(p + 4) = b;
}

// ============================================================
// Kernel 2: flash attention, split-KV.
// 2048 warps: h(4) x split(8) x wq(64). Each thread owns queries i0, i0+32.
// Per j: K/V rows broadcast across warp as float4 loads.
// ============================================================
__global__ void __launch_bounds__(256) flash_kernel()
{
    int gw = blockIdx.x * 8 + (threadIdx.x >> 5);
    int lane = threadIdx.x & 31;
    int h = gw >> 9;
    int rem = gw & 511;
    int split = rem >> 6;
    int wq = rem & 63;
    int i0 = wq * 64 + lane;
    int i1 = i0 + 32;

    float q0[32], q1[32], acc0[32], acc1[32];
    const float4* q0p = (const float4*)(g_qt + (size_t)(h * NPOS + i0) * DHEAD);
    const float4* q1p = (const float4*)(g_qt + (size_t)(h * NPOS + i1) * DHEAD);
#pragma unroll
    for (int t = 0; t < 8; t++) {
        float4 f = q0p[t];
        q0[4 * t] = f.x; q0[4 * t + 1] = f.y; q0[4 * t + 2] = f.z; q0[4 * t + 3] = f.w;
        float4 g = q1p[t];
        q1[4 * t] = g.x; q1[4 * t + 1] = g.y; q1[4 * t + 2] = g.z; q1[4 * t + 3] = g.w;
    }
#pragma unroll
    for (int d = 0; d < 32; d++) { acc0[d] = 0.f; acc1[d] = 0.f; }

    float m0 = -1e30f, m1 = -1e30f, l0 = 0.f, l1 = 0.f;

    int j0 = split * CHUNK;
    const float4* kp = (const float4*)(g_kt + (size_t)(h * NPOS + j0) * DHEAD);
    const float4* vp = (const float4*)(g_vt + (size_t)(h * NPOS + j0) * DHEAD);

    for (int j = 0; j < CHUNK; j++) {
        float s0 = 0.f, s1 = 0.f;
#pragma unroll
        for (int t = 0; t < 8; t++) {
            float4 kk = kp[j * 8 + t];
            s0 += q0[4 * t] * kk.x; s0 += q0[4 * t + 1] * kk.y;
            s0 += q0[4 * t + 2] * kk.z; s0 += q0[4 * t + 3] * kk.w;
            s1 += q1[4 * t] * kk.x; s1 += q1[4 * t + 1] * kk.y;
            s1 += q1[4 * t + 2] * kk.z; s1 += q1[4 * t + 3] * kk.w;
        }

        float p0, p1;
        if (s0 > m0) {
            float corr = exp2f((m0 - s0) * L2E);
            l0 *= corr; m0 = s0; p0 = 1.f;
#pragma unroll
            for (int d = 0; d < 32; d++) acc0[d] *= corr;
        } else {
            p0 = exp2f((s0 - m0) * L2E);
        }
        if (s1 > m1) {
            float corr = exp2f((m1 - s1) * L2E);
            l1 *= corr; m1 = s1; p1 = 1.f;
#pragma unroll
            for (int d = 0; d < 32; d++) acc1[d] *= corr;
        } else {
            p1 = exp2f((s1 - m1) * L2E);
        }
        l0 += p0; l1 += p1;

#pragma unroll
        for (int t = 0; t < 8; t++) {
            float4 vv = vp[j * 8 + t];
            acc0[4 * t]     += p0 * vv.x; acc0[4 * t + 1] += p0 * vv.y;
            acc0[4 * t + 2] += p0 * vv.z; acc0[4 * t + 3] += p0 * vv.w;
            acc1[4 * t]     += p1 * vv.x; acc1[4 * t + 1] += p1 * vv.y;
            acc1[4 * t + 2] += p1 * vv.z; acc1[4 * t + 3] += p1 * vv.w;
        }
    }

    int pi0 = (h * NPOS + i0) * NSPLIT + split;
    int pi1 = (h * NPOS + i1) * NSPLIT + split;
    g_pm[pi0] = m0; g_pl[pi0] = l0;
    g_pm[pi1] = m1; g_pl[pi1] = l1;
    float4* pa0 = (float4*)(g_pacc + (size_t)pi0 * 32);
    float4* pa1 = (float4*)(g_pacc + (size_t)pi1 * 32);
#pragma unroll
    for (int t = 0; t < 8; t++) {
        pa0[t] = make_float4(acc0[4 * t], acc0[4 * t + 1], acc0[4 * t + 2], acc0[4 * t + 3]);
        pa1[t] = make_float4(acc1[4 * t], acc1[4 * t + 1], acc1[4 * t + 2], acc1[4 * t + 3]);
    }
}

// ============================================================
// Kernel 3: combine NSPLIT partials per (h,i); write O in [c][n] layout
// ============================================================
__global__ void reduce_kernel()
{
    int idx = blockIdx.x * 128 + threadIdx.x;   // 0..16383 == h*4096+i
    int h = idx >> 12;
    int i = idx & 4095;
    int base = idx * NSPLIT;

    float M = -1e30f;
#pragma unroll
    for (int s = 0; s < NSPLIT; s++) M = fmaxf(M, g_pm[base + s]);

    float L = 0.f;
    float num[32];
#pragma unroll
    for (int d = 0; d < 32; d++) num[d] = 0.f;

#pragma unroll
    for (int s = 0; s < NSPLIT; s++) {
        float es = exp2f((g_pm[base + s] - M) * L2E);
        L += g_pl[base + s] * es;
        const float4* pa = (const float4*)(g_pacc + (size_t)(base + s) * 32);
#pragma unroll
        for (int t = 0; t < 8; t++) {
            float4 a = pa[t];
            num[4 * t]     += a.x * es; num[4 * t + 1] += a.y * es;
            num[4 * t + 2] += a.z * es; num[4 * t + 3] += a.w * es;
        }
    }
    float inv = 1.f / L;
#pragma unroll
    for (int d = 0; d < 32; d++)
        g_o[(size_t)(h * DHEAD + d) * NPOS + i] = num[d] * inv;
}

// ============================================================
// Kernel 4: y = w_out @ O + b_out   (64x128 * 128x4096)
// grid (32, 8), block 128, 8 o per thread.
// ============================================================
__global__ void outproj_kernel(const float* __restrict__ w, const float* __restrict__ b,
                               float* __restrict__ y)
{
    int n = blockIdx.x * 128 + threadIdx.x;
    int og = blockIdx.y * 8;

    __shared__ float ws[8 * 128];
    for (int idx = threadIdx.x; idx < 8 * 128; idx += 128)
        ws[idx] = w[og * 128 + idx];
    __syncthreads();

    float acc[8];
#pragma unroll
    for (int k = 0; k < 8; k++) acc[k] = b[og + k];

#pragma unroll 4
    for (int c = 0; c < HID; c++) {
        float ov = g_o[(size_t)c * NPOS + n];
#pragma unroll
        for (int k = 0; k < 8; k++) acc[k] += ws[k * 128 + c] * ov;
    }
#pragma unroll
    for (int k = 0; k < 8; k++)
        y[(size_t)(og + k) * NPOS + n] = acc[k];
}

// ============================================================
extern "C" void kernel_launch(void* const* d_in, const int* in_sizes, int n_in,
                              void* d_out, int out_size)
{
    const float* x     = (const float*)d_in[0];
    const float* w_qkv = (const float*)d_in[1];
    const float* w_out = (const float*)d_in[2];
    const float* b_out = (const float*)d_in[3];
    float* y = (float*)d_out;

    qkv_kernel<<<dim3(NPOS / 128, 48), 128>>>(x, w_qkv);
    flash_kernel<<<256, 256>>>();
    reduce_kernel<<<128, 128>>>();
    outproj_kernel<<<dim3(NPOS / 128, 8), 128>>>(w_out, b_out, y);
}

// round 5
// speedup vs baseline: 1.7639x; 1.7639x over previous
#include <cuda_runtime.h>

#define HEADS 4
#define DHEAD 32
#define HID 128
#define CIN 64
#define NPOS 4096
#define NSPLIT 4
#define CHUNK (NPOS / NSPLIT) /* 1024 */
#define L2E 1.4426950408889634f

// ---- device scratch (allocation-free: static __device__ globals) ----
__device__ __align__(16) float g_qt[HEADS * NPOS * DHEAD];   // scaled Q, [h][n][d]
__device__ __align__(16) float g_kt[HEADS * NPOS * DHEAD];   // [h][n][d]
__device__ __align__(16) float g_vt[HEADS * NPOS * DHEAD];   // [h][n][d]
__device__ float g_pm[HEADS * NPOS * NSPLIT];
__device__ float g_pl[HEADS * NPOS * NSPLIT];
__device__ __align__(16) float g_pacc[HEADS * NPOS * NSPLIT * DHEAD];
__device__ __align__(16) float g_o[HID * NPOS];              // attention out, [c][n]

// ============================================================
// Kernel 1: QKV = w_qkv @ x   (384x64 * 64x4096), write transposed tiles
// ============================================================
__global__ void qkv_kernel(const float* __restrict__ x, const float* __restrict__ w)
{
    int n = blockIdx.x * 128 + threadIdx.x;
    int og = blockIdx.y * 8;

    __shared__ float ws[8 * 64];
    for (int idx = threadIdx.x; idx < 8 * 64; idx += 128)
        ws[idx] = w[og * 64 + idx];
    __syncthreads();

    float acc[8];
#pragma unroll
    for (int k = 0; k < 8; k++) acc[k] = 0.f;

#pragma unroll 4
    for (int c = 0; c < CIN; c++) {
        float xv = x[c * NPOS + n];
#pragma unroll
        for (int k = 0; k < 8; k++) acc[k] += ws[k * 64 + c] * xv;
    }

    int seg = og >> 7;          // 0=q 1=k 2=v
    int oo = og & 127;
    int h = oo >> 5, d0 = oo & 31;
    float scale = (seg == 0) ? 0.17677669529663687f : 1.f;  // 32^-0.5
    float* base = (seg == 0) ? g_qt : ((seg == 1) ? g_kt : g_vt);

    float4 a = make_float4(acc[0] * scale, acc[1] * scale, acc[2] * scale, acc[3] * scale);
    float4 b = make_float4(acc[4] * scale, acc[5] * scale, acc[6] * scale, acc[7] * scale);
    float* p = base + (size_t)(h * NPOS + n) * DHEAD + d0;
    *(float4*)p = a;
    *(float4*)(p + 4) = b;
}

// ============================================================
// Kernel 2: flash attention, split-KV. ONE query per thread (no spills).
// grid 256 blocks x 256 threads = 65536 threads:
//   block = h(4) x split(4) x qb(16); thread owns query qb*256+tid.
// K/V rows broadcast across warp as float4 LDG (L1 broadcast).
// 4 partial dot-product accumulators break the RAW chain.
// ============================================================
__global__ void __launch_bounds__(256) flash_kernel()
{
    int bx = blockIdx.x;
    int qb = bx & 15;
    int split = (bx >> 4) & 3;
    int h = bx >> 6;
    int i = qb * 256 + threadIdx.x;

    float q[32], acc[32];
    const float4* qp = (const float4*)(g_qt + (size_t)(h * NPOS + i) * DHEAD);
#pragma unroll
    for (int t = 0; t < 8; t++) {
        float4 f = qp[t];
        q[4 * t] = f.x; q[4 * t + 1] = f.y; q[4 * t + 2] = f.z; q[4 * t + 3] = f.w;
    }
#pragma unroll
    for (int d = 0; d < 32; d++) acc[d] = 0.f;

    float m = -1e30f, l = 0.f;

    const float4* kp = (const float4*)(g_kt + (size_t)(h * NPOS + split * CHUNK) * DHEAD);
    const float4* vp = (const float4*)(g_vt + (size_t)(h * NPOS + split * CHUNK) * DHEAD);

    for (int j = 0; j < CHUNK; j++) {
        // 4 independent partial sums -> 8-deep FMA chains instead of 32
        float sa = 0.f, sb = 0.f, sc = 0.f, sd = 0.f;
#pragma unroll
        for (int t = 0; t < 8; t += 4) {
            float4 k0 = kp[j * 8 + t + 0];
            float4 k1 = kp[j * 8 + t + 1];
            float4 k2 = kp[j * 8 + t + 2];
            float4 k3 = kp[j * 8 + t + 3];
            sa += q[4 * t + 0]  * k0.x; sa += q[4 * t + 1]  * k0.y;
            sa += q[4 * t + 2]  * k0.z; sa += q[4 * t + 3]  * k0.w;
            sb += q[4 * t + 4]  * k1.x; sb += q[4 * t + 5]  * k1.y;
            sb += q[4 * t + 6]  * k1.z; sb += q[4 * t + 7]  * k1.w;
            sc += q[4 * t + 8]  * k2.x; sc += q[4 * t + 9]  * k2.y;
            sc += q[4 * t + 10] * k2.z; sc += q[4 * t + 11] * k2.w;
            sd += q[4 * t + 12] * k3.x; sd += q[4 * t + 13] * k3.y;
            sd += q[4 * t + 14] * k3.z; sd += q[4 * t + 15] * k3.w;
        }
        float s = (sa + sb) + (sc + sd);

        float p;
        if (s > m) {                       // rare after warmup (~log n times)
            float corr = exp2f((m - s) * L2E);
            l *= corr; m = s; p = 1.f;
#pragma unroll
            for (int d = 0; d < 32; d++) acc[d] *= corr;
        } else {
            p = exp2f((s - m) * L2E);
        }
        l += p;

#pragma unroll
        for (int t = 0; t < 8; t++) {
            float4 vv = vp[j * 8 + t];
            acc[4 * t]     += p * vv.x; acc[4 * t + 1] += p * vv.y;
            acc[4 * t + 2] += p * vv.z; acc[4 * t + 3] += p * vv.w;
        }
    }

    int pi = (h * NPOS + i) * NSPLIT + split;
    g_pm[pi] = m; g_pl[pi] = l;
    float4* pa = (float4*)(g_pacc + (size_t)pi * 32);
#pragma unroll
    for (int t = 0; t < 8; t++)
        pa[t] = make_float4(acc[4 * t], acc[4 * t + 1], acc[4 * t + 2], acc[4 * t + 3]);
}

// ============================================================
// Kernel 3: combine NSPLIT partials per (h,i); write O in [c][n] layout
// ============================================================
__global__ void reduce_kernel()
{
    int idx = blockIdx.x * 128 + threadIdx.x;   // 0..16383 == h*4096+i
    int h = idx >> 12;
    int i = idx & 4095;
    int base = idx * NSPLIT;

    float M = -1e30f;
#pragma unroll
    for (int s = 0; s < NSPLIT; s++) M = fmaxf(M, g_pm[base + s]);

    float L = 0.f;
    float num[32];
#pragma unroll
    for (int d = 0; d < 32; d++) num[d] = 0.f;

#pragma unroll
    for (int s = 0; s < NSPLIT; s++) {
        float es = exp2f((g_pm[base + s] - M) * L2E);
        L += g_pl[base + s] * es;
        const float4* pa = (const float4*)(g_pacc + (size_t)(base + s) * 32);
#pragma unroll
        for (int t = 0; t < 8; t++) {
            float4 a = pa[t];
            num[4 * t]     += a.x * es; num[4 * t + 1] += a.y * es;
            num[4 * t + 2] += a.z * es; num[4 * t + 3] += a.w * es;
        }
    }
    float inv = 1.f / L;
#pragma unroll
    for (int d = 0; d < 32; d++)
        g_o[(size_t)(h * DHEAD + d) * NPOS + i] = num[d] * inv;
}

// ============================================================
// Kernel 4: y = w_out @ O + b_out   (64x128 * 128x4096)
// ============================================================
__global__ void outproj_kernel(const float* __restrict__ w, const float* __restrict__ b,
                               float* __restrict__ y)
{
    int n = blockIdx.x * 128 + threadIdx.x;
    int og = blockIdx.y * 8;

    __shared__ float ws[8 * 128];
    for (int idx = threadIdx.x; idx < 8 * 128; idx += 128)
        ws[idx] = w[og * 128 + idx];
    __syncthreads();

    float acc[8];
#pragma unroll
    for (int k = 0; k < 8; k++) acc[k] = b[og + k];

#pragma unroll 4
    for (int c = 0; c < HID; c++) {
        float ov = g_o[(size_t)c * NPOS + n];
#pragma unroll
        for (int k = 0; k < 8; k++) acc[k] += ws[k * 128 + c] * ov;
    }
#pragma unroll
    for (int k = 0; k < 8; k++)
        y[(size_t)(og + k) * NPOS + n] = acc[k];
}

// ============================================================
extern "C" void kernel_launch(void* const* d_in, const int* in_sizes, int n_in,
                              void* d_out, int out_size)
{
    const float* x     = (const float*)d_in[0];
    const float* w_qkv = (const float*)d_in[1];
    const float* w_out = (const float*)d_in[2];
    const float* b_out = (const float*)d_in[3];
    float* y = (float*)d_out;

    qkv_kernel<<<dim3(NPOS / 128, 48), 128>>>(x, w_qkv);
    flash_kernel<<<256, 256>>>();
    reduce_kernel<<<128, 128>>>();
    outproj_kernel<<<dim3(NPOS / 128, 8), 128>>>(w_out, b_out, y);
}

// round 6
// speedup vs baseline: 3.6825x; 2.0877x over previous
#include <cuda_runtime.h>

#define HEADS 4
#define DHEAD 32
#define HID 128
#define CIN 64
#define NPOS 4096
#define NSPLIT 4
#define CHUNK (NPOS / NSPLIT) /* 1024 */
#define KTILE 64               /* keys per smem tile */
#define NTILES (CHUNK / KTILE) /* 16 */
#define L2E 1.4426950408889634f

typedef unsigned long long f32x2_t;

__device__ __forceinline__ f32x2_t fma2(f32x2_t a, f32x2_t b, f32x2_t c) {
    f32x2_t d;
    asm("fma.rn.f32x2 %0, %1, %2, %3;" : "=l"(d) : "l"(a), "l"(b), "l"(c));
    return d;
}
__device__ __forceinline__ f32x2_t mul2(f32x2_t a, f32x2_t b) {
    f32x2_t d;
    asm("mul.rn.f32x2 %0, %1, %2;" : "=l"(d) : "l"(a), "l"(b));
    return d;
}
__device__ __forceinline__ f32x2_t add2(f32x2_t a, f32x2_t b) {
    f32x2_t d;
    asm("add.rn.f32x2 %0, %1, %2;" : "=l"(d) : "l"(a), "l"(b));
    return d;
}
__device__ __forceinline__ f32x2_t pack2(float lo, float hi) {
    f32x2_t d;
    asm("mov.b64 %0, {%1, %2};" : "=l"(d) : "f"(lo), "f"(hi));
    return d;
}
__device__ __forceinline__ void unpack2(f32x2_t v, float& lo, float& hi) {
    asm("mov.b64 {%0, %1}, %2;" : "=f"(lo), "=f"(hi) : "l"(v));
}

// ---- device scratch ----
__device__ __align__(16) float g_qt[HEADS * NPOS * DHEAD];   // scaled Q, [h][n][d]
__device__ __align__(16) float g_kt[HEADS * NPOS * DHEAD];
__device__ __align__(16) float g_vt[HEADS * NPOS * DHEAD];
__device__ float g_pm[HEADS * NPOS * NSPLIT];
__device__ float g_pl[HEADS * NPOS * NSPLIT];
__device__ __align__(16) float g_pacc[HEADS * NPOS * NSPLIT * DHEAD];
__device__ __align__(16) float g_o[HID * NPOS];              // attention out, [c][n]

// ============================================================
// Kernel 1: QKV = w_qkv @ x  (384x64 * 64x4096), write transposed tiles
// ============================================================
__global__ void qkv_kernel(const float* __restrict__ x, const float* __restrict__ w)
{
    int n = blockIdx.x * 128 + threadIdx.x;
    int og = blockIdx.y * 8;

    __shared__ float ws[8 * 64];
    for (int idx = threadIdx.x; idx < 8 * 64; idx += 128)
        ws[idx] = w[og * 64 + idx];
    __syncthreads();

    float acc[8];
#pragma unroll
    for (int k = 0; k < 8; k++) acc[k] = 0.f;

#pragma unroll 4
    for (int c = 0; c < CIN; c++) {
        float xv = x[c * NPOS + n];
#pragma unroll
        for (int k = 0; k < 8; k++) acc[k] += ws[k * 64 + c] * xv;
    }

    int seg = og >> 7;          // 0=q 1=k 2=v
    int oo = og & 127;
    int h = oo >> 5, d0 = oo & 31;
    float scale = (seg == 0) ? 0.17677669529663687f : 1.f;  // 32^-0.5
    float* base = (seg == 0) ? g_qt : ((seg == 1) ? g_kt : g_vt);

    float4 a = make_float4(acc[0] * scale, acc[1] * scale, acc[2] * scale, acc[3] * scale);
    float4 b = make_float4(acc[4] * scale, acc[5] * scale, acc[6] * scale, acc[7] * scale);
    float* p = base + (size_t)(h * NPOS + n) * DHEAD + d0;
    *(float4*)p = a;
    *(float4*)(p + 4) = b;
}

// ============================================================
// Kernel 2: flash attention, split-KV, f32x2 packed math + SMEM K/V tiles.
// grid 256: block = h(4) x split(4) x qb(16); thread owns query qb*256+tid.
// Per key tile (64 rows): cooperative load K/V to SMEM, then each thread
// does 16 FFMA2 (QK) + 16 FFMA2 (PV) per key, K/V rows via LDS broadcast.
// ============================================================
__global__ void __launch_bounds__(256) flash_kernel()
{
    __shared__ float4 sK[KTILE * 8];   // 64 rows x 32 floats = 8KB
    __shared__ float4 sV[KTILE * 8];

    int bx = blockIdx.x;
    int qb = bx & 15;
    int split = (bx >> 4) & 3;
    int h = bx >> 6;
    int tid = threadIdx.x;
    int i = qb * 256 + tid;

    f32x2_t q2[16], acc2[16];
    {
        const ulonglong2* qp = (const ulonglong2*)(g_qt + (size_t)(h * NPOS + i) * DHEAD);
#pragma unroll
        for (int t = 0; t < 8; t++) {
            ulonglong2 f = qp[t];
            q2[2 * t] = f.x; q2[2 * t + 1] = f.y;
        }
    }
#pragma unroll
    for (int t = 0; t < 16; t++) acc2[t] = 0ull;   // two packed 0.0f

    float m = -1e30f, l = 0.f;

    const float4* kg = (const float4*)g_kt + (size_t)(h * NPOS + split * CHUNK) * 8;
    const float4* vg = (const float4*)g_vt + (size_t)(h * NPOS + split * CHUNK) * 8;

    for (int tile = 0; tile < NTILES; tile++) {
        __syncthreads();   // previous tile's consumers done
        sK[tid]       = kg[tile * 512 + tid];
        sK[tid + 256] = kg[tile * 512 + 256 + tid];
        sV[tid]       = vg[tile * 512 + tid];
        sV[tid + 256] = vg[tile * 512 + 256 + tid];
        __syncthreads();

#pragma unroll 2
        for (int jj = 0; jj < KTILE; jj++) {
            // ---- QK dot: 16 packed FMAs, 4 independent chains ----
            f32x2_t s0 = 0ull, s1 = 0ull, s2 = 0ull, s3 = 0ull;
            const ulonglong2* kr = (const ulonglong2*)(sK + jj * 8);
#pragma unroll
            for (int t = 0; t < 8; t += 2) {
                ulonglong2 ka = kr[t];
                ulonglong2 kb = kr[t + 1];
                s0 = fma2(q2[2 * t],     ka.x, s0);
                s1 = fma2(q2[2 * t + 1], ka.y, s1);
                s2 = fma2(q2[2 * t + 2], kb.x, s2);
                s3 = fma2(q2[2 * t + 3], kb.y, s3);
            }
            f32x2_t sp = add2(add2(s0, s2), add2(s1, s3));
            float slo, shi;
            unpack2(sp, slo, shi);
            float s = slo + shi;

            // ---- online softmax (rescale branch rarely taken) ----
            float p;
            if (s > m) {
                float corr = exp2f((m - s) * L2E);
                l *= corr; m = s; p = 1.f;
                f32x2_t c2 = pack2(corr, corr);
#pragma unroll
                for (int t = 0; t < 16; t++) acc2[t] = mul2(acc2[t], c2);
            } else {
                p = exp2f((s - m) * L2E);
            }
            l += p;

            // ---- PV accumulate: 16 packed FMAs ----
            f32x2_t p2 = pack2(p, p);
            const ulonglong2* vr = (const ulonglong2*)(sV + jj * 8);
#pragma unroll
            for (int t = 0; t < 8; t++) {
                ulonglong2 vv = vr[t];
                acc2[2 * t]     = fma2(p2, vv.x, acc2[2 * t]);
                acc2[2 * t + 1] = fma2(p2, vv.y, acc2[2 * t + 1]);
            }
        }
    }

    int pi = (h * NPOS + i) * NSPLIT + split;
    g_pm[pi] = m; g_pl[pi] = l;
    ulonglong2* pa = (ulonglong2*)(g_pacc + (size_t)pi * 32);
#pragma unroll
    for (int t = 0; t < 8; t++) {
        ulonglong2 o;
        o.x = acc2[2 * t]; o.y = acc2[2 * t + 1];
        pa[t] = o;
    }
}

// ============================================================
// Kernel 3: combine NSPLIT partials per (h,i); write O in [c][n] layout
// ============================================================
__global__ void reduce_kernel()
{
    int idx = blockIdx.x * 128 + threadIdx.x;   // h*4096+i
    int h = idx >> 12;
    int i = idx & 4095;
    int base = idx * NSPLIT;

    float M = -1e30f;
#pragma unroll
    for (int s = 0; s < NSPLIT; s++) M = fmaxf(M, g_pm[base + s]);

    float L = 0.f;
    float num[32];
#pragma unroll
    for (int d = 0; d < 32; d++) num[d] = 0.f;

#pragma unroll
    for (int s = 0; s < NSPLIT; s++) {
        float es = exp2f((g_pm[base + s] - M) * L2E);
        L += g_pl[base + s] * es;
        const float4* pa = (const float4*)(g_pacc + (size_t)(base + s) * 32);
#pragma unroll
        for (int t = 0; t < 8; t++) {
            float4 a = pa[t];
            num[4 * t]     += a.x * es; num[4 * t + 1] += a.y * es;
            num[4 * t + 2] += a.z * es; num[4 * t + 3] += a.w * es;
        }
    }
    float inv = 1.f / L;
#pragma unroll
    for (int d = 0; d < 32; d++)
        g_o[(size_t)(h * DHEAD + d) * NPOS + i] = num[d] * inv;
}

// ============================================================
// Kernel 4: y = w_out @ O + b_out   (64x128 * 128x4096)
// ============================================================
__global__ void outproj_kernel(const float* __restrict__ w, const float* __restrict__ b,
                               float* __restrict__ y)
{
    int n = blockIdx.x * 128 + threadIdx.x;
    int og = blockIdx.y * 8;

    __shared__ float ws[8 * 128];
    for (int idx = threadIdx.x; idx < 8 * 128; idx += 128)
        ws[idx] = w[og * 128 + idx];
    __syncthreads();

    float acc[8];
#pragma unroll
    for (int k = 0; k < 8; k++) acc[k] = b[og + k];

#pragma unroll 4
    for (int c = 0; c < HID; c++) {
        float ov = g_o[(size_t)c * NPOS + n];
#pragma unroll
        for (int k = 0; k < 8; k++) acc[k] += ws[k * 128 + c] * ov;
    }
#pragma unroll
    for (int k = 0; k < 8; k++)
        y[(size_t)(og + k) * NPOS + n] = acc[k];
}

// ============================================================
extern "C" void kernel_launch(void* const* d_in, const int* in_sizes, int n_in,
                              void* d_out, int out_size)
{
    const float* x     = (const float*)d_in[0];
    const float* w_qkv = (const float*)d_in[1];
    const float* w_out = (const float*)d_in[2];
    const float* b_out = (const float*)d_in[3];
    float* y = (float*)d_out;

    qkv_kernel<<<dim3(NPOS / 128, 48), 128>>>(x, w_qkv);
    flash_kernel<<<256, 256>>>();
    reduce_kernel<<<128, 128>>>();
    outproj_kernel<<<dim3(NPOS / 128, 8), 128>>>(w_out, b_out, y);
}

// round 9
// speedup vs baseline: 13.3506x; 3.6254x over previous
#include <cuda_runtime.h>
#include <cuda_bf16.h>

#define HEADS 4
#define DHEAD 32
#define HID 128
#define CIN 64
#define NPOS 4096
#define NSPLIT 4
#define CHUNK (NPOS / NSPLIT) /* 1024 */
#define KT 64                 /* keys per smem tile */
#define NTILES (CHUNK / KT)   /* 16 */
#define L2E 1.4426950408889634f

typedef unsigned int uint32;

// ---- device scratch ----
__device__ __align__(16) __nv_bfloat16 g_qtb[HEADS * NPOS * DHEAD]; // [h][n][d], scaled
__device__ __align__(16) __nv_bfloat16 g_ktb[HEADS * NPOS * DHEAD]; // [h][n][d]
__device__ __align__(16) __nv_bfloat16 g_vtb[HEADS * DHEAD * NPOS]; // [h][d][n] (transposed!)
__device__ float g_pm[HEADS * NPOS * NSPLIT];
__device__ float g_pl[HEADS * NPOS * NSPLIT];
__device__ __align__(16) float g_pacc[HEADS * NPOS * NSPLIT * DHEAD];
__device__ __align__(16) float g_o[HID * NPOS];                     // attention out fp32 [c][n]

// m16n8k16 bf16 MMA, fp32 accum, D==C in-place
__device__ __forceinline__ void mma16816(float* d, const uint32* a, uint32 b0, uint32 b1)
{
    asm volatile(
        "mma.sync.aligned.m16n8k16.row.col.f32.bf16.bf16.f32 "
        "{%0,%1,%2,%3},{%4,%5,%6,%7},{%8,%9},{%0,%1,%2,%3};"
        : "+f"(d[0]), "+f"(d[1]), "+f"(d[2]), "+f"(d[3])
        : "r"(a[0]), "r"(a[1]), "r"(a[2]), "r"(a[3]), "r"(b0), "r"(b1));
}

__device__ __forceinline__ uint32 pk2(float lo, float hi)
{
    __nv_bfloat162 t = __floats2bfloat162_rn(lo, hi);  // x=lo(low half), y=hi
    return *(uint32*)&t;
}

// ============================================================
// Kernel 1: QKV = w_qkv @ x (384x64 * 64x4096), fp32 math, bf16 stores.
// Q,K -> [h][n][32]; V -> [h][d][n] (transposed for PV MMA B-operand).
// ============================================================
__global__ void qkv_kernel(const float* __restrict__ x, const float* __restrict__ w)
{
    int n = blockIdx.x * 128 + threadIdx.x;
    int og = blockIdx.y * 8;

    __shared__ float ws[8 * 64];
    for (int idx = threadIdx.x; idx < 8 * 64; idx += 128)
        ws[idx] = w[og * 64 + idx];
    __syncthreads();

    float acc[8];
#pragma unroll
    for (int k = 0; k < 8; k++) acc[k] = 0.f;

#pragma unroll 4
    for (int c = 0; c < CIN; c++) {
        float xv = x[c * NPOS + n];
#pragma unroll
        for (int k = 0; k < 8; k++) acc[k] += ws[k * 64 + c] * xv;
    }

    int seg = og >> 7;          // 0=q 1=k 2=v
    int oo = og & 127;
    int h = oo >> 5, d0 = oo & 31;

    if (seg < 2) {
        float scale = (seg == 0) ? 0.17677669529663687f : 1.f;  // 32^-0.5 on Q
        __nv_bfloat162 h0 = __floats2bfloat162_rn(acc[0] * scale, acc[1] * scale);
        __nv_bfloat162 h1 = __floats2bfloat162_rn(acc[2] * scale, acc[3] * scale);
        __nv_bfloat162 h2 = __floats2bfloat162_rn(acc[4] * scale, acc[5] * scale);
        __nv_bfloat162 h3 = __floats2bfloat162_rn(acc[6] * scale, acc[7] * scale);
        uint4 pk;
        pk.x = *(uint32*)&h0; pk.y = *(uint32*)&h1;
        pk.z = *(uint32*)&h2; pk.w = *(uint32*)&h3;
        __nv_bfloat16* base = (seg == 0 ? g_qtb : g_ktb) + (size_t)(h * NPOS + n) * DHEAD + d0;
        *(uint4*)base = pk;
    } else {
#pragma unroll
        for (int k = 0; k < 8; k++)
            g_vtb[(size_t)(h * DHEAD + d0 + k) * NPOS + n] = __float2bfloat16(acc[k]);
    }
}

// ============================================================
// Kernel 2: tensor-core flash attention (bf16 mma.sync, fp32 accum).
// grid 512: bx = h(4) x split(4) x qblk(32). Block 256 = 8 warps,
// each warp owns 16 queries, loops CHUNK keys in 64-key SMEM tiles.
// ============================================================
__global__ void __launch_bounds__(256) flash_kernel()
{
    __shared__ __nv_bfloat16 sK[KT * 40];      // [64 keys][32 d], rows padded to 80B
    __shared__ __nv_bfloat16 sVt[DHEAD * 72];  // [32 d][64 keys], rows padded to 144B
    uint32* sKu = (uint32*)sK;
    uint32* sVu = (uint32*)sVt;

    int bx = blockIdx.x;
    int qblk = bx & 31, split = (bx >> 5) & 3, h = bx >> 7;
    int tid = threadIdx.x, w = tid >> 5, lane = tid & 31;
    int g = lane >> 2, tg = lane & 3;
    int q0 = qblk * 128 + w * 16;

    // Q fragments (row-major A): rows q0+g, q0+g+8; cols 2tg(+8)(+16ks)
    uint32 qa[2][4];
    {
        const uint32* Qb = (const uint32*)g_qtb + (size_t)(h * NPOS + q0) * 16;
#pragma unroll
        for (int ks = 0; ks < 2; ks++) {
            qa[ks][0] = Qb[g * 16 + tg + 8 * ks];
            qa[ks][1] = Qb[(g + 8) * 16 + tg + 8 * ks];
            qa[ks][2] = Qb[g * 16 + tg + 4 + 8 * ks];
            qa[ks][3] = Qb[(g + 8) * 16 + tg + 4 + 8 * ks];
        }
    }

    float o[4][4];
#pragma unroll
    for (int a = 0; a < 4; a++)
#pragma unroll
        for (int b = 0; b < 4; b++) o[a][b] = 0.f;
    float m0 = -1e30f, m1 = -1e30f, l0 = 0.f, l1 = 0.f;

    const uint32* Kg = (const uint32*)g_ktb + (size_t)(h * NPOS + split * CHUNK) * 16;
    const uint32* Vg = (const uint32*)g_vtb + (size_t)(h * DHEAD) * (NPOS / 2) + split * (CHUNK / 2);

    for (int tile = 0; tile < NTILES; tile++) {
        __syncthreads();
        // stage K tile: 64 rows x 16 uints
#pragma unroll
        for (int it = 0; it < 4; it++) {
            int idx = tid + it * 256;
            int row = idx >> 4, c = idx & 15;
            sKu[row * 20 + c] = Kg[(size_t)(tile * 64 + row) * 16 + c];
        }
        // stage Vt tile: 32 rows x 32 uints
#pragma unroll
        for (int it = 0; it < 4; it++) {
            int idx = tid + it * 256;
            int row = idx >> 5, c = idx & 31;
            sVu[row * 36 + c] = Vg[(size_t)row * (NPOS / 2) + tile * 32 + c];
        }
        __syncthreads();

#pragma unroll
        for (int kt = 0; kt < 4; kt++) {    // 16-key subtiles
            // ---- S = Q @ K^T : 16x16 tile as two n8 MMAs x two k-steps ----
            float s[2][4];
#pragma unroll
            for (int nt = 0; nt < 2; nt++)
#pragma unroll
                for (int c = 0; c < 4; c++) s[nt][c] = 0.f;

#pragma unroll
            for (int ks = 0; ks < 2; ks++) {
#pragma unroll
                for (int nt = 0; nt < 2; nt++) {
                    int krow = kt * 16 + nt * 8 + g;
                    uint32 b0 = sKu[krow * 20 + tg + 8 * ks];
                    uint32 b1 = sKu[krow * 20 + tg + 4 + 8 * ks];
                    mma16816(s[nt], qa[ks], b0, b1);
                }
            }

            // ---- online softmax on fragments ----
            // row g holds c0,c1 of both n-tiles; row g+8 holds c2,c3
            float tm0 = fmaxf(fmaxf(s[0][0], s[0][1]), fmaxf(s[1][0], s[1][1]));
            float tm1 = fmaxf(fmaxf(s[0][2], s[0][3]), fmaxf(s[1][2], s[1][3]));
            tm0 = fmaxf(tm0, __shfl_xor_sync(0xffffffffu, tm0, 1));
            tm0 = fmaxf(tm0, __shfl_xor_sync(0xffffffffu, tm0, 2));
            tm1 = fmaxf(tm1, __shfl_xor_sync(0xffffffffu, tm1, 1));
            tm1 = fmaxf(tm1, __shfl_xor_sync(0xffffffffu, tm1, 2));
            float nm0 = fmaxf(m0, tm0), nm1 = fmaxf(m1, tm1);
            float c0 = exp2f((m0 - nm0) * L2E);
            float c1 = exp2f((m1 - nm1) * L2E);
            m0 = nm0; m1 = nm1;

            float p00 = exp2f((s[0][0] - nm0) * L2E);
            float p01 = exp2f((s[0][1] - nm0) * L2E);
            float p10 = exp2f((s[1][0] - nm0) * L2E);
            float p11 = exp2f((s[1][1] - nm0) * L2E);
            float p02 = exp2f((s[0][2] - nm1) * L2E);
            float p03 = exp2f((s[0][3] - nm1) * L2E);
            float p12 = exp2f((s[1][2] - nm1) * L2E);
            float p13 = exp2f((s[1][3] - nm1) * L2E);

            l0 = l0 * c0 + ((p00 + p01) + (p10 + p11));
            l1 = l1 * c1 + ((p02 + p03) + (p12 + p13));

#pragma unroll
            for (int nt = 0; nt < 4; nt++) {
                o[nt][0] *= c0; o[nt][1] *= c0;
                o[nt][2] *= c1; o[nt][3] *= c1;
            }

            // ---- P fragment (bf16) reuses S fragment layout as MMA A ----
            uint32 pa[4];
            pa[0] = pk2(p00, p01);   // P[g][2tg..2tg+1]        (keys 0-7)
            pa[1] = pk2(p02, p03);   // P[g+8][2tg..2tg+1]
            pa[2] = pk2(p10, p11);   // P[g][2tg+8..2tg+9]      (keys 8-15)
            pa[3] = pk2(p12, p13);   // P[g+8][2tg+8..2tg+9]

            // ---- O += P @ V : 4 d-chunks of 8 ----
#pragma unroll
            for (int nt = 0; nt < 4; nt++) {
                int vrow = nt * 8 + g;
                uint32 b0 = sVu[vrow * 36 + kt * 8 + tg];
                uint32 b1 = sVu[vrow * 36 + kt * 8 + tg + 4];
                mma16816(o[nt], pa, b0, b1);
            }
        }
    }

    // finalize row sums across the quad (rows are spread over lanes tg=0..3)
    l0 += __shfl_xor_sync(0xffffffffu, l0, 1);
    l0 += __shfl_xor_sync(0xffffffffu, l0, 2);
    l1 += __shfl_xor_sync(0xffffffffu, l1, 1);
    l1 += __shfl_xor_sync(0xffffffffu, l1, 2);

    int qg0 = h * NPOS + q0 + g;
    int qg1 = qg0 + 8;
    int pi0 = qg0 * NSPLIT + split;
    int pi1 = qg1 * NSPLIT + split;
    g_pm[pi0] = m0; g_pl[pi0] = l0;
    g_pm[pi1] = m1; g_pl[pi1] = l1;

    float2* P0 = (float2*)(g_pacc + (size_t)pi0 * 32);
    float2* P1 = (float2*)(g_pacc + (size_t)pi1 * 32);
#pragma unroll
    for (int nt = 0; nt < 4; nt++) {
        P0[nt * 4 + tg] = make_float2(o[nt][0], o[nt][1]);  // d = nt*8 + 2tg
        P1[nt * 4 + tg] = make_float2(o[nt][2], o[nt][3]);
    }
}

// ============================================================
// Kernel 3: combine NSPLIT partials per (h,i); write O in [c][n] layout
// ============================================================
__global__ void reduce_kernel()
{
    int idx = blockIdx.x * 128 + threadIdx.x;   // h*4096+i
    int h = idx >> 12;
    int i = idx & 4095;
    int base = idx * NSPLIT;

    float M = -1e30f;
#pragma unroll
    for (int s = 0; s < NSPLIT; s++) M = fmaxf(M, g_pm[base + s]);

    float L = 0.f;
    float num[32];
#pragma unroll
    for (int d = 0; d < 32; d++) num[d] = 0.f;

#pragma unroll
    for (int s = 0; s < NSPLIT; s++) {
        float es = exp2f((g_pm[base + s] - M) * L2E);
        L += g_pl[base + s] * es;
        const float4* pa = (const float4*)(g_pacc + (size_t)(base + s) * 32);
#pragma unroll
        for (int t = 0; t < 8; t++) {
            float4 a = pa[t];
            num[4 * t]     += a.x * es; num[4 * t + 1] += a.y * es;
            num[4 * t + 2] += a.z * es; num[4 * t + 3] += a.w * es;
        }
    }
    float inv = 1.f / L;
#pragma unroll
    for (int d = 0; d < 32; d++)
        g_o[(size_t)(h * DHEAD + d) * NPOS + i] = num[d] * inv;
}

// ============================================================
// Kernel 4: y = w_out @ O + b_out   (64x128 * 128x4096)
// ============================================================
__global__ void outproj_kernel(const float* __restrict__ w, const float* __restrict__ b,
                               float* __restrict__ y)
{
    int n = blockIdx.x * 128 + threadIdx.x;
    int og = blockIdx.y * 8;

    __shared__ float ws[8 * 128];
    for (int idx = threadIdx.x; idx < 8 * 128; idx += 128)
        ws[idx] = w[og * 128 + idx];
    __syncthreads();

    float acc[8];
#pragma unroll
    for (int k = 0; k < 8; k++) acc[k] = b[og + k];

#pragma unroll 4
    for (int c = 0; c < HID; c++) {
        float ov = g_o[(size_t)c * NPOS + n];
#pragma unroll
        for (int k = 0; k < 8; k++) acc[k] += ws[k * 128 + c] * ov;
    }
#pragma unroll
    for (int k = 0; k < 8; k++)
        y[(size_t)(og + k) * NPOS + n] = acc[k];
}

// ============================================================
extern "C" void kernel_launch(void* const* d_in, const int* in_sizes, int n_in,
                              void* d_out, int out_size)
{
    const float* x     = (const float*)d_in[0];
    const float* w_qkv = (const float*)d_in[1];
    const float* w_out = (const float*)d_in[2];
    const float* b_out = (const float*)d_in[3];
    float* y = (float*)d_out;

    qkv_kernel<<<dim3(NPOS / 128, 48), 128>>>(x, w_qkv);
    flash_kernel<<<512, 256>>>();
    reduce_kernel<<<128, 128>>>();
    outproj_kernel<<<dim3(NPOS / 128, 8), 128>>>(w_out, b_out, y);
}